// round 11
// baseline (speedup 1.0000x reference)
#include <cuda_runtime.h>
#include <cuda_bf16.h>
#include <cstdint>

#define MROWS 10000
#define MPAD  10048          // 157 * 64
#define KDIM  256
#define NF    64
#define N1R   8192
#define KH    5

// t = x @ W scratch, fp32 [10048 x 64] = 2.57 MB (L2-resident)
__device__ float g_t[MPAD * NF];

static __device__ __forceinline__ uint32_t smem_cast(const void* p) {
    return (uint32_t)__cvta_generic_to_shared(p);
}
static __device__ __forceinline__ void ldsm_x4(uint32_t* r, uint32_t addr) {
    asm volatile("ldmatrix.sync.aligned.m8n8.x4.shared.b16 {%0,%1,%2,%3}, [%4];"
                 : "=r"(r[0]), "=r"(r[1]), "=r"(r[2]), "=r"(r[3]) : "r"(addr));
}
static __device__ __forceinline__ void ldsm_x4_t(uint32_t* r, uint32_t addr) {
    asm volatile("ldmatrix.sync.aligned.m8n8.x4.trans.shared.b16 {%0,%1,%2,%3}, [%4];"
                 : "=r"(r[0]), "=r"(r[1]), "=r"(r[2]), "=r"(r[3]) : "r"(addr));
}
static __device__ __forceinline__ void mma_bf16(float* d, const uint32_t* a,
                                                uint32_t b0, uint32_t b1) {
    asm volatile("mma.sync.aligned.m16n8k16.row.col.f32.bf16.bf16.f32 "
                 "{%0,%1,%2,%3}, {%4,%5,%6,%7}, {%8,%9}, {%0,%1,%2,%3};"
                 : "+f"(d[0]), "+f"(d[1]), "+f"(d[2]), "+f"(d[3])
                 : "r"(a[0]), "r"(a[1]), "r"(a[2]), "r"(a[3]), "r"(b0), "r"(b1));
}

// ---------------------------------------------------------------------------
// Kernel 1: t = x @ W via 3-pass Markidis bf16 split on tensor cores (HMMA).
// t = Ahi*Bhi + Ahi*Blo + Alo*Bhi, fp32 accum; dropped lo*lo ~ 1.5e-5 rel.
// CTA: 4 warps, BM=64 rows x full N=64; warp w = rows w*16..w*16+15.
// K in 8 chunks of 32: fp32 load -> reg split -> bf16 smem -> ldmatrix -> mma.
// Smem strides 40 (A) / 72 (B) keep every ldmatrix phase conflict-free and
// every address 16B-aligned.
// ---------------------------------------------------------------------------
__global__ __launch_bounds__(128) void gemm_bf16_kernel(const float* __restrict__ x,
                                                        const float* __restrict__ w) {
    __shared__ __nv_bfloat16 Ahi[64][40], Alo[64][40];   // 64x32 used
    __shared__ __nv_bfloat16 Bhi[32][72], Blo[32][72];   // 32x64 used

    const int tid  = threadIdx.x;
    const int wid  = tid >> 5;
    const int lane = tid & 31;
    const int row0 = blockIdx.x * 64;

    const float4* x4 = (const float4*)x;   // row stride 64 float4
    const float4* w4 = (const float4*)w;   // row stride 16 float4

    float d[8][4] = {};                    // 8 n-chunks of m16n8 fp32 frags

    // ldmatrix source addresses (per-thread constants modulo ko/nc offsets)
    const int a_row = wid * 16 + (lane & 15);
    const int a_col = (lane >> 4) << 3;            // +ko
    const int b_row = (lane & 7) + (lane & 8);     // +ko
    const int b_col = (lane >> 4) << 3;            // +nc*16

    #pragma unroll 1
    for (int kc = 0; kc < 8; kc++) {
        const int k0 = kc * 32;

        // ---- stage A tile [64 x 32] fp32 -> hi/lo bf16 ----
        #pragma unroll
        for (int j = 0; j < 4; j++) {
            int idx = tid + j * 128;               // 0..511
            int r = idx >> 3, c4 = idx & 7;
            int grow = row0 + r;
            float4 v = (grow < MROWS)
                     ? x4[(size_t)grow * 64 + kc * 8 + c4]
                     : make_float4(0.f, 0.f, 0.f, 0.f);
            float hx = __bfloat162float(__float2bfloat16_rn(v.x));
            float hy = __bfloat162float(__float2bfloat16_rn(v.y));
            float hz = __bfloat162float(__float2bfloat16_rn(v.z));
            float hw = __bfloat162float(__float2bfloat16_rn(v.w));
            *(__nv_bfloat162*)&Ahi[r][c4 * 4 + 0] = __floats2bfloat162_rn(hx, hy);
            *(__nv_bfloat162*)&Ahi[r][c4 * 4 + 2] = __floats2bfloat162_rn(hz, hw);
            *(__nv_bfloat162*)&Alo[r][c4 * 4 + 0] = __floats2bfloat162_rn(v.x - hx, v.y - hy);
            *(__nv_bfloat162*)&Alo[r][c4 * 4 + 2] = __floats2bfloat162_rn(v.z - hz, v.w - hw);
        }
        // ---- stage B tile [32 x 64] fp32 -> hi/lo bf16 ----
        #pragma unroll
        for (int j = 0; j < 4; j++) {
            int idx = tid + j * 128;               // 0..511
            int kk = idx >> 4, c4 = idx & 15;
            float4 v = w4[(size_t)(k0 + kk) * 16 + c4];
            float hx = __bfloat162float(__float2bfloat16_rn(v.x));
            float hy = __bfloat162float(__float2bfloat16_rn(v.y));
            float hz = __bfloat162float(__float2bfloat16_rn(v.z));
            float hw = __bfloat162float(__float2bfloat16_rn(v.w));
            *(__nv_bfloat162*)&Bhi[kk][c4 * 4 + 0] = __floats2bfloat162_rn(hx, hy);
            *(__nv_bfloat162*)&Bhi[kk][c4 * 4 + 2] = __floats2bfloat162_rn(hz, hw);
            *(__nv_bfloat162*)&Blo[kk][c4 * 4 + 0] = __floats2bfloat162_rn(v.x - hx, v.y - hy);
            *(__nv_bfloat162*)&Blo[kk][c4 * 4 + 2] = __floats2bfloat162_rn(v.z - hz, v.w - hw);
        }
        __syncthreads();

        // ---- mma over the two k16 halves of this chunk ----
        #pragma unroll
        for (int h = 0; h < 2; h++) {
            const int ko = h * 16;
            uint32_t ah[4], al[4];
            ldsm_x4(ah, smem_cast(&Ahi[a_row][ko + a_col]));
            ldsm_x4(al, smem_cast(&Alo[a_row][ko + a_col]));
            #pragma unroll
            for (int nc = 0; nc < 4; nc++) {
                uint32_t bh[4], bl[4];
                ldsm_x4_t(bh, smem_cast(&Bhi[ko + b_row][nc * 16 + b_col]));
                ldsm_x4_t(bl, smem_cast(&Blo[ko + b_row][nc * 16 + b_col]));
                mma_bf16(d[nc * 2 + 0], ah, bh[0], bh[1]);   // hi*hi
                mma_bf16(d[nc * 2 + 1], ah, bh[2], bh[3]);
                mma_bf16(d[nc * 2 + 0], ah, bl[0], bl[1]);   // hi*lo
                mma_bf16(d[nc * 2 + 1], ah, bl[2], bl[3]);
                mma_bf16(d[nc * 2 + 0], al, bh[0], bh[1]);   // lo*hi
                mma_bf16(d[nc * 2 + 1], al, bh[2], bh[3]);
            }
        }
        __syncthreads();
    }

    // ---- epilogue: D frag -> g_t (scratch covers padded rows; qq < 10000) ----
    const int r  = lane >> 2;
    const int c2 = (lane & 3) * 2;
    const int rbase = row0 + wid * 16;
    #pragma unroll
    for (int n8 = 0; n8 < 8; n8++) {
        *(float2*)&g_t[(size_t)(rbase + r) * NF + n8 * 8 + c2] =
            make_float2(d[n8][0], d[n8][1]);
        *(float2*)&g_t[(size_t)(rbase + r + 8) * NF + n8 * 8 + c2] =
            make_float2(d[n8][2], d[n8][3]);
    }
}

// ---------------------------------------------------------------------------
// Kernel 2: out[i,:] = sum_{k<5} t[qq[5i+k],:] + 5*bias
// (floor(softmax/1000) == 0 identically => e == G exactly; 5 ones per row.)
// 16 threads per row (one float4 each); 2 rows per thread -> 10 independent
// L2 gathers in flight. 256 CTAs x 256 threads.
// ---------------------------------------------------------------------------
__global__ __launch_bounds__(256) void gather_kernel(const int* __restrict__ qq,
                                                     const float* __restrict__ bias,
                                                     float* __restrict__ out) {
    const int tid = threadIdx.x;
    const int lr  = tid >> 4;            // 0..15
    const int cg  = tid & 15;            // float4 column
    const int i0  = blockIdx.x * 32 + lr;
    const int i1  = i0 + 16;

    const float4* t4 = (const float4*)g_t;
    const int* qa = qq + i0 * KH;
    const int* qb = qq + i1 * KH;

    float4 a0 = t4[(size_t)qa[0] * 16 + cg];
    float4 a1 = t4[(size_t)qa[1] * 16 + cg];
    float4 a2 = t4[(size_t)qa[2] * 16 + cg];
    float4 a3 = t4[(size_t)qa[3] * 16 + cg];
    float4 a4 = t4[(size_t)qa[4] * 16 + cg];
    float4 b0 = t4[(size_t)qb[0] * 16 + cg];
    float4 b1 = t4[(size_t)qb[1] * 16 + cg];
    float4 b2 = t4[(size_t)qb[2] * 16 + cg];
    float4 b3 = t4[(size_t)qb[3] * 16 + cg];
    float4 b4 = t4[(size_t)qb[4] * 16 + cg];

    float4 bv = ((const float4*)bias)[cg];
    float4 oA, oB;
    oA.x = a0.x + a1.x + a2.x + a3.x + a4.x + 5.0f * bv.x;
    oA.y = a0.y + a1.y + a2.y + a3.y + a4.y + 5.0f * bv.y;
    oA.z = a0.z + a1.z + a2.z + a3.z + a4.z + 5.0f * bv.z;
    oA.w = a0.w + a1.w + a2.w + a3.w + a4.w + 5.0f * bv.w;
    oB.x = b0.x + b1.x + b2.x + b3.x + b4.x + 5.0f * bv.x;
    oB.y = b0.y + b1.y + b2.y + b3.y + b4.y + 5.0f * bv.y;
    oB.z = b0.z + b1.z + b2.z + b3.z + b4.z + 5.0f * bv.z;
    oB.w = b0.w + b1.w + b2.w + b3.w + b4.w + 5.0f * bv.w;

    ((float4*)out)[(size_t)i0 * 16 + cg] = oA;
    ((float4*)out)[(size_t)i1 * 16 + cg] = oB;
}

// ---------------------------------------------------------------------------
// Inputs (metadata order):
//   0: x [10000,256] f32, 1: G (unused), 2: weight [256,64] f32,
//   3: a (unused — attention branch identically zero), 4: bias [64] f32,
//   5: qq [40960] i32, 6: rows (unused)
// output: [8192,64] f32
// out = G@x@W + 5*bias  (floor(softmax/1000) == 0 => e == G, 5 ones/row)
// ---------------------------------------------------------------------------
extern "C" void kernel_launch(void* const* d_in, const int* in_sizes, int n_in,
                              void* d_out, int out_size) {
    const float* x    = (const float*)d_in[0];
    const float* w    = (const float*)d_in[2];
    const float* bias = (const float*)d_in[4];
    const int*   qq   = (const int*)d_in[5];
    float*       out  = (float*)d_out;

    gemm_bf16_kernel<<<MPAD / 64, 128>>>(x, w);
    gather_kernel<<<N1R / 32, 256>>>(qq, bias, out);
}

// round 12
// speedup vs baseline: 1.5532x; 1.5532x over previous
#include <cuda_runtime.h>
#include <cuda_bf16.h>
#include <cstdint>

#define KDIM   256
#define NF     64
#define N1R    8192
#define KH     5
#define BM     32
#define CK     64               // K chunk
#define NCHUNK (KDIM / CK)      // 4

static __device__ __forceinline__ uint32_t smem_cast(const void* p) {
    return (uint32_t)__cvta_generic_to_shared(p);
}
static __device__ __forceinline__ void ldsm_x4(uint32_t* r, uint32_t addr) {
    asm volatile("ldmatrix.sync.aligned.m8n8.x4.shared.b16 {%0,%1,%2,%3}, [%4];"
                 : "=r"(r[0]), "=r"(r[1]), "=r"(r[2]), "=r"(r[3]) : "r"(addr));
}
static __device__ __forceinline__ void ldsm_x4_t(uint32_t* r, uint32_t addr) {
    asm volatile("ldmatrix.sync.aligned.m8n8.x4.trans.shared.b16 {%0,%1,%2,%3}, [%4];"
                 : "=r"(r[0]), "=r"(r[1]), "=r"(r[2]), "=r"(r[3]) : "r"(addr));
}
static __device__ __forceinline__ void mma_bf16(float* d, const uint32_t* a,
                                                uint32_t b0, uint32_t b1) {
    asm volatile("mma.sync.aligned.m16n8k16.row.col.f32.bf16.bf16.f32 "
                 "{%0,%1,%2,%3}, {%4,%5,%6,%7}, {%8,%9}, {%0,%1,%2,%3};"
                 : "+f"(d[0]), "+f"(d[1]), "+f"(d[2]), "+f"(d[3])
                 : "r"(a[0]), "r"(a[1]), "r"(a[2]), "r"(a[3]), "r"(b0), "r"(b1));
}

// ---------------------------------------------------------------------------
// SINGLE fused kernel: out = G @ x @ W + 5*bias
// (floor(softmax/1000) == 0 identically => e == G; G rows = 5 ones at qq.)
// Order: s = gather-sum of x rows (fp32) -> Markidis bf16 split -> HMMA.
// Each CTA's 32 output rows depend only on its own gathers => no scratch,
// no second launch, no global barrier (kills the recurring ~5-7us tax).
// 256 CTAs (86% wave efficiency) x 128 thr; ~28KB smem -> ~6 CTAs/SM, so
// co-resident CTAs hide each other's staging latency (R11's missing piece).
// 3-term split (hi*hi + hi*lo + lo*hi, fp32 accum): rel err ~1e-5 << 1e-3.
// Warp w: rows (w&1)*16..+15, cols (w>>1)*32..+31 of the CTA tile.
// ---------------------------------------------------------------------------
__global__ __launch_bounds__(128) void fused_tc_kernel(const float* __restrict__ x,
                                                       const int* __restrict__ qq,
                                                       const float* __restrict__ w,
                                                       const float* __restrict__ bias,
                                                       float* __restrict__ out) {
    __shared__ __nv_bfloat16 Ahi[BM][72], Alo[BM][72];   // s chunk [32 x 64]
    __shared__ __nv_bfloat16 Bhi[CK][72], Blo[CK][72];   // W chunk [64 x 64]
    __shared__ int qs[BM * KH];

    const int tid  = threadIdx.x;
    const int wid  = tid >> 5;
    const int lane = tid & 31;
    const int r0   = blockIdx.x * BM;
    const int m0   = (wid & 1) * 16;
    const int n0   = (wid >> 1) * 32;

    for (int t = tid; t < BM * KH; t += 128) qs[t] = qq[r0 * KH + t];
    __syncthreads();

    const float4* x4 = (const float4*)x;   // row stride 64 float4
    const float4* w4 = (const float4*)w;   // row stride 16 float4

    float d[4][4] = {};                    // 4 n8-frags of m16n8

    const int a_row = m0 + (lane & 15);
    const int a_col = (lane >> 4) << 3;
    const int b_row = (lane & 7) + (lane & 8);
    const int b_col = (lane >> 4) << 3;

    #pragma unroll 1
    for (int c = 0; c < NCHUNK; c++) {
        // ---- stage A: gather-sum 32 rows x 64 cols (512 float4 slots) ----
        #pragma unroll
        for (int j = 0; j < 4; j++) {
            int idx = tid + j * 128;               // 0..511
            int row = idx >> 4, c4 = idx & 15;
            const int* q = &qs[row * KH];
            const float4* xp = x4 + c * 16 + c4;
            float4 a0 = xp[(size_t)q[0] * 64];
            float4 a1 = xp[(size_t)q[1] * 64];
            float4 a2 = xp[(size_t)q[2] * 64];
            float4 a3 = xp[(size_t)q[3] * 64];
            float4 a4 = xp[(size_t)q[4] * 64];
            float sx = a0.x + a1.x + a2.x + a3.x + a4.x;
            float sy = a0.y + a1.y + a2.y + a3.y + a4.y;
            float sz = a0.z + a1.z + a2.z + a3.z + a4.z;
            float sw = a0.w + a1.w + a2.w + a3.w + a4.w;
            float hx = __bfloat162float(__float2bfloat16_rn(sx));
            float hy = __bfloat162float(__float2bfloat16_rn(sy));
            float hz = __bfloat162float(__float2bfloat16_rn(sz));
            float hw = __bfloat162float(__float2bfloat16_rn(sw));
            *(__nv_bfloat162*)&Ahi[row][c4 * 4 + 0] = __floats2bfloat162_rn(hx, hy);
            *(__nv_bfloat162*)&Ahi[row][c4 * 4 + 2] = __floats2bfloat162_rn(hz, hw);
            *(__nv_bfloat162*)&Alo[row][c4 * 4 + 0] = __floats2bfloat162_rn(sx - hx, sy - hy);
            *(__nv_bfloat162*)&Alo[row][c4 * 4 + 2] = __floats2bfloat162_rn(sz - hz, sw - hw);
        }
        // ---- stage B: W chunk [64 x 64] (1024 float4 slots) ----
        #pragma unroll
        for (int j = 0; j < 8; j++) {
            int idx = tid + j * 128;               // 0..1023
            int kk = idx >> 4, c4 = idx & 15;
            float4 v = w4[(size_t)(c * CK + kk) * 16 + c4];
            float hx = __bfloat162float(__float2bfloat16_rn(v.x));
            float hy = __bfloat162float(__float2bfloat16_rn(v.y));
            float hz = __bfloat162float(__float2bfloat16_rn(v.z));
            float hw = __bfloat162float(__float2bfloat16_rn(v.w));
            *(__nv_bfloat162*)&Bhi[kk][c4 * 4 + 0] = __floats2bfloat162_rn(hx, hy);
            *(__nv_bfloat162*)&Bhi[kk][c4 * 4 + 2] = __floats2bfloat162_rn(hz, hw);
            *(__nv_bfloat162*)&Blo[kk][c4 * 4 + 0] = __floats2bfloat162_rn(v.x - hx, v.y - hy);
            *(__nv_bfloat162*)&Blo[kk][c4 * 4 + 2] = __floats2bfloat162_rn(v.z - hz, v.w - hw);
        }
        __syncthreads();

        // ---- mma: 4 k16 steps per chunk ----
        #pragma unroll
        for (int ko = 0; ko < CK; ko += 16) {
            uint32_t ah[4], al[4];
            ldsm_x4(ah, smem_cast(&Ahi[a_row][ko + a_col]));
            ldsm_x4(al, smem_cast(&Alo[a_row][ko + a_col]));
            #pragma unroll
            for (int nc = 0; nc < 2; nc++) {
                uint32_t bh[4], bl[4];
                ldsm_x4_t(bh, smem_cast(&Bhi[ko + b_row][n0 + nc * 16 + b_col]));
                ldsm_x4_t(bl, smem_cast(&Blo[ko + b_row][n0 + nc * 16 + b_col]));
                mma_bf16(d[nc * 2 + 0], ah, bh[0], bh[1]);   // hi*hi
                mma_bf16(d[nc * 2 + 1], ah, bh[2], bh[3]);
                mma_bf16(d[nc * 2 + 0], ah, bl[0], bl[1]);   // hi*lo
                mma_bf16(d[nc * 2 + 1], ah, bl[2], bl[3]);
                mma_bf16(d[nc * 2 + 0], al, bh[0], bh[1]);   // lo*hi
                mma_bf16(d[nc * 2 + 1], al, bh[2], bh[3]);
            }
        }
        __syncthreads();
    }

    // ---- epilogue: frag -> out with + 5*bias (rows all valid: 8192 % 32 == 0) ----
    const int fr  = lane >> 2;             // 0..7
    const int fc2 = (lane & 3) * 2;
    #pragma unroll
    for (int n8 = 0; n8 < 4; n8++) {
        int col = n0 + n8 * 8 + fc2;
        float2 bv = *(const float2*)&bias[col];
        int rowA = r0 + m0 + fr;
        int rowB = rowA + 8;
        *(float2*)&out[(size_t)rowA * NF + col] =
            make_float2(d[n8][0] + 5.0f * bv.x, d[n8][1] + 5.0f * bv.y);
        *(float2*)&out[(size_t)rowB * NF + col] =
            make_float2(d[n8][2] + 5.0f * bv.x, d[n8][3] + 5.0f * bv.y);
    }
}

// ---------------------------------------------------------------------------
// Inputs (metadata order):
//   0: x [10000,256] f32, 1: G (unused), 2: weight [256,64] f32,
//   3: a (unused — attention branch identically zero), 4: bias [64] f32,
//   5: qq [40960] i32, 6: rows (unused)
// output: [8192,64] f32
// ---------------------------------------------------------------------------
extern "C" void kernel_launch(void* const* d_in, const int* in_sizes, int n_in,
                              void* d_out, int out_size) {
    const float* x    = (const float*)d_in[0];
    const float* w    = (const float*)d_in[2];
    const float* bias = (const float*)d_in[4];
    const int*   qq   = (const int*)d_in[5];
    float*       out  = (float*)d_out;

    fused_tc_kernel<<<N1R / BM, 128>>>(x, qq, w, bias, out);
}

// round 13
// speedup vs baseline: 1.5767x; 1.0151x over previous
#include <cuda_runtime.h>
#include <cuda_bf16.h>
#include <cstdint>

#define KDIM   256
#define NF     64
#define N1R    8192
#define KH     5
#define BM     32
#define CK     64               // K chunk
#define NCHUNK (KDIM / CK)      // 4
#define NTHR   256

static __device__ __forceinline__ uint32_t smem_cast(const void* p) {
    return (uint32_t)__cvta_generic_to_shared(p);
}
static __device__ __forceinline__ void ldsm_x4(uint32_t* r, uint32_t addr) {
    asm volatile("ldmatrix.sync.aligned.m8n8.x4.shared.b16 {%0,%1,%2,%3}, [%4];"
                 : "=r"(r[0]), "=r"(r[1]), "=r"(r[2]), "=r"(r[3]) : "r"(addr));
}
static __device__ __forceinline__ void ldsm_x4_t(uint32_t* r, uint32_t addr) {
    asm volatile("ldmatrix.sync.aligned.m8n8.x4.trans.shared.b16 {%0,%1,%2,%3}, [%4];"
                 : "=r"(r[0]), "=r"(r[1]), "=r"(r[2]), "=r"(r[3]) : "r"(addr));
}
static __device__ __forceinline__ void mma_bf16(float* d, const uint32_t* a,
                                                uint32_t b0, uint32_t b1) {
    asm volatile("mma.sync.aligned.m16n8k16.row.col.f32.bf16.bf16.f32 "
                 "{%0,%1,%2,%3}, {%4,%5,%6,%7}, {%8,%9}, {%0,%1,%2,%3};"
                 : "+f"(d[0]), "+f"(d[1]), "+f"(d[2]), "+f"(d[3])
                 : "r"(a[0]), "r"(a[1]), "r"(a[2]), "r"(a[3]), "r"(b0), "r"(b1));
}

// ---------------------------------------------------------------------------
// SINGLE fused kernel: out = G @ x @ W + 5*bias
// (floor(softmax/1000) == 0 identically => e == G; G rows = 5 ones at qq.)
// s = gather-sum of x rows (fp32) -> Markidis bf16 split -> HMMA (3 passes:
// hi*hi + hi*lo + lo*hi, fp32 accum; rel err ~1e-5 << 1e-3).
//
// R12 lesson: 4 warps/CTA at <=2 CTAs/SM = 7 warps/SM, occ 10.6%, issue 11%
// -> pure latency exposure. Here: 256 threads (8 warps) per CTA, same 256
// CTAs and smem, ~14 warps/SM; per-thread staging work halves; regs ~55.
// Warp w: rows (w&1)*16..+15, cols (w>>1)*16..+15 of the CTA tile.
// ---------------------------------------------------------------------------
__global__ __launch_bounds__(NTHR) void fused_tc_kernel(const float* __restrict__ x,
                                                        const int* __restrict__ qq,
                                                        const float* __restrict__ w,
                                                        const float* __restrict__ bias,
                                                        float* __restrict__ out) {
    __shared__ __nv_bfloat16 Ahi[BM][72], Alo[BM][72];   // s chunk [32 x 64]
    __shared__ __nv_bfloat16 Bhi[CK][72], Blo[CK][72];   // W chunk [64 x 64]
    __shared__ int qs[BM * KH];

    const int tid  = threadIdx.x;
    const int wid  = tid >> 5;
    const int lane = tid & 31;
    const int r0   = blockIdx.x * BM;
    const int m0   = (wid & 1) * 16;
    const int n0   = (wid >> 1) * 16;

    for (int t = tid; t < BM * KH; t += NTHR) qs[t] = qq[r0 * KH + t];
    __syncthreads();

    const float4* x4 = (const float4*)x;   // row stride 64 float4
    const float4* w4 = (const float4*)w;   // row stride 16 float4

    float d[2][4] = {};                    // 2 n8-frags of m16n8

    const int a_row = m0 + (lane & 15);
    const int a_col = (lane >> 4) << 3;
    const int b_row = (lane & 7) + (lane & 8);
    const int b_col = (lane >> 4) << 3;

    #pragma unroll 1
    for (int c = 0; c < NCHUNK; c++) {
        // ---- stage A: gather-sum 32 rows x 64 cols (512 float4 slots) ----
        #pragma unroll
        for (int j = 0; j < 2; j++) {
            int idx = tid + j * NTHR;              // 0..511
            int row = idx >> 4, c4 = idx & 15;
            const int* q = &qs[row * KH];
            const float4* xp = x4 + c * 16 + c4;
            float4 a0 = xp[(size_t)q[0] * 64];
            float4 a1 = xp[(size_t)q[1] * 64];
            float4 a2 = xp[(size_t)q[2] * 64];
            float4 a3 = xp[(size_t)q[3] * 64];
            float4 a4 = xp[(size_t)q[4] * 64];
            float sx = a0.x + a1.x + a2.x + a3.x + a4.x;
            float sy = a0.y + a1.y + a2.y + a3.y + a4.y;
            float sz = a0.z + a1.z + a2.z + a3.z + a4.z;
            float sw = a0.w + a1.w + a2.w + a3.w + a4.w;
            float hx = __bfloat162float(__float2bfloat16_rn(sx));
            float hy = __bfloat162float(__float2bfloat16_rn(sy));
            float hz = __bfloat162float(__float2bfloat16_rn(sz));
            float hw = __bfloat162float(__float2bfloat16_rn(sw));
            *(__nv_bfloat162*)&Ahi[row][c4 * 4 + 0] = __floats2bfloat162_rn(hx, hy);
            *(__nv_bfloat162*)&Ahi[row][c4 * 4 + 2] = __floats2bfloat162_rn(hz, hw);
            *(__nv_bfloat162*)&Alo[row][c4 * 4 + 0] = __floats2bfloat162_rn(sx - hx, sy - hy);
            *(__nv_bfloat162*)&Alo[row][c4 * 4 + 2] = __floats2bfloat162_rn(sz - hz, sw - hw);
        }
        // ---- stage B: W chunk [64 x 64] (1024 float4 slots) ----
        #pragma unroll
        for (int j = 0; j < 4; j++) {
            int idx = tid + j * NTHR;              // 0..1023
            int kk = idx >> 4, c4 = idx & 15;
            float4 v = w4[(size_t)(c * CK + kk) * 16 + c4];
            float hx = __bfloat162float(__float2bfloat16_rn(v.x));
            float hy = __bfloat162float(__float2bfloat16_rn(v.y));
            float hz = __bfloat162float(__float2bfloat16_rn(v.z));
            float hw = __bfloat162float(__float2bfloat16_rn(v.w));
            *(__nv_bfloat162*)&Bhi[kk][c4 * 4 + 0] = __floats2bfloat162_rn(hx, hy);
            *(__nv_bfloat162*)&Bhi[kk][c4 * 4 + 2] = __floats2bfloat162_rn(hz, hw);
            *(__nv_bfloat162*)&Blo[kk][c4 * 4 + 0] = __floats2bfloat162_rn(v.x - hx, v.y - hy);
            *(__nv_bfloat162*)&Blo[kk][c4 * 4 + 2] = __floats2bfloat162_rn(v.z - hz, v.w - hw);
        }
        __syncthreads();

        // ---- mma: 4 k16 steps per chunk, warp tile m16 x n16 ----
        #pragma unroll
        for (int ko = 0; ko < CK; ko += 16) {
            uint32_t ah[4], al[4], bh[4], bl[4];
            ldsm_x4(ah, smem_cast(&Ahi[a_row][ko + a_col]));
            ldsm_x4(al, smem_cast(&Alo[a_row][ko + a_col]));
            ldsm_x4_t(bh, smem_cast(&Bhi[ko + b_row][n0 + b_col]));
            ldsm_x4_t(bl, smem_cast(&Blo[ko + b_row][n0 + b_col]));
            mma_bf16(d[0], ah, bh[0], bh[1]);   // hi*hi
            mma_bf16(d[1], ah, bh[2], bh[3]);
            mma_bf16(d[0], ah, bl[0], bl[1]);   // hi*lo
            mma_bf16(d[1], ah, bl[2], bl[3]);
            mma_bf16(d[0], al, bh[0], bh[1]);   // lo*hi
            mma_bf16(d[1], al, bh[2], bh[3]);
        }
        __syncthreads();
    }

    // ---- epilogue: frag -> out with + 5*bias ----
    const int fr  = lane >> 2;             // 0..7
    const int fc2 = (lane & 3) * 2;
    #pragma unroll
    for (int n8 = 0; n8 < 2; n8++) {
        int col = n0 + n8 * 8 + fc2;
        float2 bv = *(const float2*)&bias[col];
        int rowA = r0 + m0 + fr;
        int rowB = rowA + 8;
        *(float2*)&out[(size_t)rowA * NF + col] =
            make_float2(d[n8][0] + 5.0f * bv.x, d[n8][1] + 5.0f * bv.y);
        *(float2*)&out[(size_t)rowB * NF + col] =
            make_float2(d[n8][2] + 5.0f * bv.x, d[n8][3] + 5.0f * bv.y);
    }
}

// ---------------------------------------------------------------------------
// Inputs (metadata order):
//   0: x [10000,256] f32, 1: G (unused), 2: weight [256,64] f32,
//   3: a (unused — attention branch identically zero), 4: bias [64] f32,
//   5: qq [40960] i32, 6: rows (unused)
// output: [8192,64] f32
// ---------------------------------------------------------------------------
extern "C" void kernel_launch(void* const* d_in, const int* in_sizes, int n_in,
                              void* d_out, int out_size) {
    const float* x    = (const float*)d_in[0];
    const float* w    = (const float*)d_in[2];
    const float* bias = (const float*)d_in[4];
    const int*   qq   = (const int*)d_in[5];
    float*       out  = (float*)d_out;

    fused_tc_kernel<<<N1R / BM, NTHR>>>(x, qq, w, bias, out);
}

// round 14
// speedup vs baseline: 1.8296x; 1.1604x over previous
#include <cuda_runtime.h>
#include <cuda_bf16.h>
#include <cstdint>

#define KDIM   256
#define NF     64
#define N1R    8192
#define KH     5
#define BM     32
#define CK     64               // K chunk
#define NCHUNK (KDIM / CK)      // 4
#define NTHR   256

static __device__ __forceinline__ uint32_t smem_cast(const void* p) {
    return (uint32_t)__cvta_generic_to_shared(p);
}
static __device__ __forceinline__ void ldsm_x4(uint32_t* r, uint32_t addr) {
    asm volatile("ldmatrix.sync.aligned.m8n8.x4.shared.b16 {%0,%1,%2,%3}, [%4];"
                 : "=r"(r[0]), "=r"(r[1]), "=r"(r[2]), "=r"(r[3]) : "r"(addr));
}
static __device__ __forceinline__ void ldsm_x4_t(uint32_t* r, uint32_t addr) {
    asm volatile("ldmatrix.sync.aligned.m8n8.x4.trans.shared.b16 {%0,%1,%2,%3}, [%4];"
                 : "=r"(r[0]), "=r"(r[1]), "=r"(r[2]), "=r"(r[3]) : "r"(addr));
}
static __device__ __forceinline__ void mma_bf16(float* d, const uint32_t* a,
                                                uint32_t b0, uint32_t b1) {
    asm volatile("mma.sync.aligned.m16n8k16.row.col.f32.bf16.bf16.f32 "
                 "{%0,%1,%2,%3}, {%4,%5,%6,%7}, {%8,%9}, {%0,%1,%2,%3};"
                 : "+f"(d[0]), "+f"(d[1]), "+f"(d[2]), "+f"(d[3])
                 : "r"(a[0]), "r"(a[1]), "r"(a[2]), "r"(a[3]), "r"(b0), "r"(b1));
}

// ---------------------------------------------------------------------------
// SINGLE fused kernel: out = G @ x @ W + 5*bias
// (floor(softmax/1000) == 0 identically => e == G; G rows = 5 ones at qq.)
// s = gather-sum of x rows (fp32) -> Markidis bf16 split -> HMMA (3 passes:
// hi*hi + hi*lo + lo*hi, fp32 accum; rel err ~1e-5 << 1e-3).
//
// R13 lesson: warp count alone didn't fix issue=13% -- the per-chunk chain
// gather(600cy) -> convert -> bar -> mma -> bar left the gather latency
// fully exposed. Here: cross-chunk REGISTER PREFETCH -- chunk c+1's global
// loads are issued right after the staging barrier, overlapping their
// latency with the mma phase and barriers. q-indices cached in registers.
// __launch_bounds__(256,2): 2 CTAs/SM (16 warps) guaranteed.
// ---------------------------------------------------------------------------
__global__ __launch_bounds__(NTHR, 2) void fused_tc_kernel(const float* __restrict__ x,
                                                           const int* __restrict__ qq,
                                                           const float* __restrict__ w,
                                                           const float* __restrict__ bias,
                                                           float* __restrict__ out) {
    __shared__ __nv_bfloat16 Ahi[BM][72], Alo[BM][72];   // s chunk [32 x 64]
    __shared__ __nv_bfloat16 Bhi[CK][72], Blo[CK][72];   // W chunk [64 x 64]
    __shared__ int qs[BM * KH];

    const int tid  = threadIdx.x;
    const int wid  = tid >> 5;
    const int lane = tid & 31;
    const int r0   = blockIdx.x * BM;
    const int m0   = (wid & 1) * 16;
    const int n0   = (wid >> 1) * 16;

    for (int t = tid; t < BM * KH; t += NTHR) qs[t] = qq[r0 * KH + t];
    __syncthreads();

    const float4* x4 = (const float4*)x;   // row stride 64 float4
    const float4* w4 = (const float4*)w;   // row stride 16 float4

    // per-thread staging coordinates + cached q indices (constant over chunks)
    int arow[2], ac4[2], qi[2][KH];
    #pragma unroll
    for (int j = 0; j < 2; j++) {
        int idx = tid + j * NTHR;          // 0..511
        arow[j] = idx >> 4; ac4[j] = idx & 15;
        #pragma unroll
        for (int t = 0; t < KH; t++) qi[j][t] = qs[arow[j] * KH + t];
    }
    const int bkk0 = tid >> 4;             // +16 per j
    const int bc4  = tid & 15;

    float4 pa[2][KH];                      // gather prefetch (10 float4)
    float4 pb[4];                          // W prefetch (4 float4)
    float  d[2][4] = {};

    const int a_row = m0 + (lane & 15);
    const int a_col = (lane >> 4) << 3;
    const int b_row = (lane & 7) + (lane & 8);
    const int b_col = (lane >> 4) << 3;

#define ISSUE(c)                                                               \
    {                                                                          \
        _Pragma("unroll")                                                      \
        for (int j = 0; j < 2; j++) {                                          \
            const float4* xp = x4 + (c) * 16 + ac4[j];                         \
            _Pragma("unroll")                                                  \
            for (int t = 0; t < KH; t++) pa[j][t] = xp[(size_t)qi[j][t] * 64]; \
        }                                                                      \
        _Pragma("unroll")                                                      \
        for (int j = 0; j < 4; j++)                                            \
            pb[j] = w4[(size_t)((c) * CK + bkk0 + j * 16) * 16 + bc4];         \
    }

    ISSUE(0);

    #pragma unroll 1
    for (int c = 0; c < NCHUNK; c++) {
        // ---- convert prefetched data -> smem tiles ----
        #pragma unroll
        for (int j = 0; j < 2; j++) {
            float sx = pa[j][0].x + pa[j][1].x + pa[j][2].x + pa[j][3].x + pa[j][4].x;
            float sy = pa[j][0].y + pa[j][1].y + pa[j][2].y + pa[j][3].y + pa[j][4].y;
            float sz = pa[j][0].z + pa[j][1].z + pa[j][2].z + pa[j][3].z + pa[j][4].z;
            float sw = pa[j][0].w + pa[j][1].w + pa[j][2].w + pa[j][3].w + pa[j][4].w;
            float hx = __bfloat162float(__float2bfloat16_rn(sx));
            float hy = __bfloat162float(__float2bfloat16_rn(sy));
            float hz = __bfloat162float(__float2bfloat16_rn(sz));
            float hw = __bfloat162float(__float2bfloat16_rn(sw));
            int row = arow[j], c4 = ac4[j];
            *(__nv_bfloat162*)&Ahi[row][c4 * 4 + 0] = __floats2bfloat162_rn(hx, hy);
            *(__nv_bfloat162*)&Ahi[row][c4 * 4 + 2] = __floats2bfloat162_rn(hz, hw);
            *(__nv_bfloat162*)&Alo[row][c4 * 4 + 0] = __floats2bfloat162_rn(sx - hx, sy - hy);
            *(__nv_bfloat162*)&Alo[row][c4 * 4 + 2] = __floats2bfloat162_rn(sz - hz, sw - hw);
        }
        #pragma unroll
        for (int j = 0; j < 4; j++) {
            float4 v = pb[j];
            float hx = __bfloat162float(__float2bfloat16_rn(v.x));
            float hy = __bfloat162float(__float2bfloat16_rn(v.y));
            float hz = __bfloat162float(__float2bfloat16_rn(v.z));
            float hw = __bfloat162float(__float2bfloat16_rn(v.w));
            int kk = bkk0 + j * 16;
            *(__nv_bfloat162*)&Bhi[kk][bc4 * 4 + 0] = __floats2bfloat162_rn(hx, hy);
            *(__nv_bfloat162*)&Bhi[kk][bc4 * 4 + 2] = __floats2bfloat162_rn(hz, hw);
            *(__nv_bfloat162*)&Blo[kk][bc4 * 4 + 0] = __floats2bfloat162_rn(v.x - hx, v.y - hy);
            *(__nv_bfloat162*)&Blo[kk][bc4 * 4 + 2] = __floats2bfloat162_rn(v.z - hz, v.w - hw);
        }
        __syncthreads();

        // ---- prefetch next chunk NOW: latency overlaps mma + barriers ----
        if (c < NCHUNK - 1) ISSUE(c + 1);

        // ---- mma: 4 k16 steps, warp tile m16 x n16 ----
        #pragma unroll
        for (int ko = 0; ko < CK; ko += 16) {
            uint32_t ah[4], al[4], bh[4], bl[4];
            ldsm_x4(ah, smem_cast(&Ahi[a_row][ko + a_col]));
            ldsm_x4(al, smem_cast(&Alo[a_row][ko + a_col]));
            ldsm_x4_t(bh, smem_cast(&Bhi[ko + b_row][n0 + b_col]));
            ldsm_x4_t(bl, smem_cast(&Blo[ko + b_row][n0 + b_col]));
            mma_bf16(d[0], ah, bh[0], bh[1]);   // hi*hi
            mma_bf16(d[1], ah, bh[2], bh[3]);
            mma_bf16(d[0], ah, bl[0], bl[1]);   // hi*lo
            mma_bf16(d[1], ah, bl[2], bl[3]);
            mma_bf16(d[0], al, bh[0], bh[1]);   // lo*hi
            mma_bf16(d[1], al, bh[2], bh[3]);
        }
        __syncthreads();
    }
#undef ISSUE

    // ---- epilogue: frag -> out with + 5*bias ----
    const int fr  = lane >> 2;             // 0..7
    const int fc2 = (lane & 3) * 2;
    #pragma unroll
    for (int n8 = 0; n8 < 2; n8++) {
        int col = n0 + n8 * 8 + fc2;
        float2 bv = *(const float2*)&bias[col];
        int rowA = r0 + m0 + fr;
        int rowB = rowA + 8;
        *(float2*)&out[(size_t)rowA * NF + col] =
            make_float2(d[n8][0] + 5.0f * bv.x, d[n8][1] + 5.0f * bv.y);
        *(float2*)&out[(size_t)rowB * NF + col] =
            make_float2(d[n8][2] + 5.0f * bv.x, d[n8][3] + 5.0f * bv.y);
    }
}

// ---------------------------------------------------------------------------
// Inputs (metadata order):
//   0: x [10000,256] f32, 1: G (unused), 2: weight [256,64] f32,
//   3: a (unused — attention branch identically zero), 4: bias [64] f32,
//   5: qq [40960] i32, 6: rows (unused)
// output: [8192,64] f32
// ---------------------------------------------------------------------------
extern "C" void kernel_launch(void* const* d_in, const int* in_sizes, int n_in,
                              void* d_out, int out_size) {
    const float* x    = (const float*)d_in[0];
    const float* w    = (const float*)d_in[2];
    const float* bias = (const float*)d_in[4];
    const int*   qq   = (const int*)d_in[5];
    float*       out  = (float*)d_out;

    fused_tc_kernel<<<N1R / BM, NTHR>>>(x, qq, w, bias, out);
}